// round 2
// baseline (speedup 1.0000x reference)
#include <cuda_runtime.h>
#include <cstdint>

#define NMAX 50000
#define EMAX 800000

// ---------------- scratch (device globals: allocation-free) ----------------
__device__ float g_h1[NMAX * 128];    // layer1 pre-act features [N,4,32]
__device__ float g_out1[NMAX * 128];  // layer1 unnormalized aggregation
__device__ float g_as1[NMAX * 4];     // alpha_src per (node, head)
__device__ float g_ad1[NMAX * 4];     // alpha_dst per (node, head)
__device__ float g_den1[NMAX * 4];    // softmax denominators, layer1
__device__ float g_h2[NMAX * 2];      // layer2 features
__device__ float g_as2[NMAX];
__device__ float g_ad2[NMAX];
__device__ float g_den2[NMAX];
__device__ float g_S2[NMAX * 2];      // layer2 unnormalized aggregation

__device__ __forceinline__ float lrelu(float v) { return v > 0.f ? v : 0.2f * v; }

__device__ __forceinline__ void red_add_v4(float* p, float4 v) {
    asm volatile("red.global.add.v4.f32 [%0], {%1,%2,%3,%4};"
                 :: "l"(p), "f"(v.x), "f"(v.y), "f"(v.z), "f"(v.w) : "memory");
}
__device__ __forceinline__ void red_add_v2(float* p, float a, float b) {
    asm volatile("red.global.add.v2.f32 [%0], {%1,%2};"
                 :: "l"(p), "f"(a), "f"(b) : "memory");
}

// ---------------- zeroing (graph replays must be idempotent) ----------------
__global__ void kzero_out1(int n) {
    int i = blockIdx.x * blockDim.x + threadIdx.x;
    if (i < n * 32) ((float4*)g_out1)[i] = make_float4(0.f, 0.f, 0.f, 0.f);
}
__global__ void kzero_small(int n) {
    int i = blockIdx.x * blockDim.x + threadIdx.x;
    if (i < n * 4) g_den1[i] = 0.f;
    if (i < n * 2) g_S2[i] = 0.f;
    if (i < n)     g_den2[i] = 0.f;
}

// ---------------- layer1 feature transform + attention logits ----------------
// block = 128 threads (one output channel each), grid-stride over nodes.
__global__ void k_feat1(const float* __restrict__ x, const float* __restrict__ W1,
                        const float* __restrict__ a_src1, const float* __restrict__ a_dst1,
                        int n_nodes) {
    __shared__ float Ws[16 * 128];
    int c = threadIdx.x;
    for (int i = c; i < 16 * 128; i += 128) Ws[i] = W1[i];
    __syncthreads();
    int lane = c & 31, head = c >> 5;
    float as = a_src1[c], ad = a_dst1[c];   // (1,4,32) flat == channel index
    for (int n = blockIdx.x; n < n_nodes; n += gridDim.x) {
        const float4* xr = (const float4*)(x + (size_t)n * 16);
        float4 x0 = xr[0], x1 = xr[1], x2 = xr[2], x3 = xr[3];
        float acc;
        acc  = x0.x * Ws[c];        acc += x0.y * Ws[128 + c];
        acc += x0.z * Ws[256 + c];  acc += x0.w * Ws[384 + c];
        acc += x1.x * Ws[512 + c];  acc += x1.y * Ws[640 + c];
        acc += x1.z * Ws[768 + c];  acc += x1.w * Ws[896 + c];
        acc += x2.x * Ws[1024 + c]; acc += x2.y * Ws[1152 + c];
        acc += x2.z * Ws[1280 + c]; acc += x2.w * Ws[1408 + c];
        acc += x3.x * Ws[1536 + c]; acc += x3.y * Ws[1664 + c];
        acc += x3.z * Ws[1792 + c]; acc += x3.w * Ws[1920 + c];
        g_h1[(size_t)n * 128 + c] = acc;
        float s = acc * as, d = acc * ad;
        #pragma unroll
        for (int o = 16; o; o >>= 1) {
            s += __shfl_down_sync(0xffffffffu, s, o);
            d += __shfl_down_sync(0xffffffffu, d, o);
        }
        if (lane == 0) { g_as1[n * 4 + head] = s; g_ad1[n * 4 + head] = d; }
    }
}

// ---------------- layer1 fused edge pass: exp(logit) -> denom + scatter ----
// one warp per edge (incl. implicit self-loops at the tail).
__global__ void k_edge1(const int* __restrict__ ei, int Eo, int n_nodes) {
    int t = blockIdx.x * blockDim.x + threadIdx.x;
    int gw = t >> 5, lane = t & 31;
    int ET = Eo + n_nodes;
    if (gw >= ET) return;
    int s, d;
    if (gw < Eo) { s = ei[gw]; d = ei[Eo + gw]; }
    else         { s = gw - Eo; d = s; }
    int head = lane >> 3;
    float w = __expf(lrelu(g_as1[s * 4 + head] + g_ad1[d * 4 + head]));
    if ((lane & 7) == 0) atomicAdd(g_den1 + d * 4 + head, w);
    float4 h = *(const float4*)(g_h1 + (size_t)s * 128 + lane * 4);
    h.x *= w; h.y *= w; h.z *= w; h.w *= w;
    red_add_v4(g_out1 + (size_t)d * 128 + lane * 4, h);
}

// ---------------- normalize + bias + relu + layer2 transform ----------------
__global__ void k_feat2(const float* __restrict__ b1, const float* __restrict__ W2,
                        const float* __restrict__ a_src2, const float* __restrict__ a_dst2,
                        int n_nodes) {
    __shared__ float red[8];
    int c = threadIdx.x, lane = c & 31, wp = c >> 5;
    float w2a = W2[c * 2], w2b = W2[c * 2 + 1];
    float bb = b1[c];
    float asa = a_src2[0], asb = a_src2[1], ada = a_dst2[0], adb = a_dst2[1];
    for (int n = blockIdx.x; n < n_nodes; n += gridDim.x) {
        float v = g_out1[(size_t)n * 128 + c] / (g_den1[n * 4 + wp] + 1e-16f) + bb;
        v = fmaxf(v, 0.f);
        float p = v * w2a, q = v * w2b;
        #pragma unroll
        for (int o = 16; o; o >>= 1) {
            p += __shfl_down_sync(0xffffffffu, p, o);
            q += __shfl_down_sync(0xffffffffu, q, o);
        }
        if (lane == 0) { red[wp * 2] = p; red[wp * 2 + 1] = q; }
        __syncthreads();
        if (c == 0) {
            float h0 = red[0] + red[2] + red[4] + red[6];
            float h1v = red[1] + red[3] + red[5] + red[7];
            g_h2[n * 2] = h0; g_h2[n * 2 + 1] = h1v;
            g_as2[n] = h0 * asa + h1v * asb;
            g_ad2[n] = h0 * ada + h1v * adb;
        }
        __syncthreads();
    }
}

// ---------------- layer2 fused edge pass (thread per edge) ------------------
__global__ void k_edge2(const int* __restrict__ ei, int Eo, int n_nodes) {
    int e = blockIdx.x * blockDim.x + threadIdx.x;
    int ET = Eo + n_nodes;
    if (e >= ET) return;
    int s, d;
    if (e < Eo) { s = ei[e]; d = ei[Eo + e]; }
    else        { s = e - Eo; d = s; }
    float w = __expf(lrelu(g_as2[s] + g_ad2[d]));
    atomicAdd(g_den2 + d, w);
    red_add_v2(g_S2 + d * 2, w * g_h2[s * 2], w * g_h2[s * 2 + 1]);
}

// ---------------- final normalize + bias -> d_out ---------------------------
__global__ void k_final(float* __restrict__ out, const float* __restrict__ b2, int n_nodes) {
    int n = blockIdx.x * blockDim.x + threadIdx.x;
    if (n >= n_nodes) return;
    float inv = 1.f / (g_den2[n] + 1e-16f);
    out[n * 2]     = g_S2[n * 2]     * inv + b2[0];
    out[n * 2 + 1] = g_S2[n * 2 + 1] * inv + b2[1];
}

extern "C" void kernel_launch(void* const* d_in, const int* in_sizes, int n_in,
                              void* d_out, int out_size) {
    const float* x   = (const float*)d_in[0];
    const int*   ei  = (const int*)d_in[1];
    const float* W1  = (const float*)d_in[2];
    const float* as1 = (const float*)d_in[3];
    const float* ad1 = (const float*)d_in[4];
    const float* b1  = (const float*)d_in[5];
    const float* W2  = (const float*)d_in[6];
    const float* as2 = (const float*)d_in[7];
    const float* ad2 = (const float*)d_in[8];
    const float* b2  = (const float*)d_in[9];
    float* out = (float*)d_out;

    int n  = in_sizes[0] / 16;   // nodes
    int Eo = in_sizes[1] / 2;    // original edges (self-loops appended implicitly)
    int ET = Eo + n;

    kzero_out1<<<(n * 32 + 255) / 256, 256>>>(n);
    kzero_small<<<(n * 4 + 255) / 256, 256>>>(n);
    k_feat1<<<1184, 128>>>(x, W1, as1, ad1, n);
    {
        long long threads = (long long)ET * 32;
        k_edge1<<<(unsigned)((threads + 255) / 256), 256>>>(ei, Eo, n);
    }
    k_feat2<<<1184, 128>>>(b1, W2, as2, ad2, n);
    k_edge2<<<(ET + 255) / 256, 256>>>(ei, Eo, n);
    k_final<<<(n + 255) / 256, 256>>>(out, b2, n);
}

// round 3
// speedup vs baseline: 1.0404x; 1.0404x over previous
#include <cuda_runtime.h>
#include <cstdint>

#define NMAX 50000
#define EMAX 800000
#define ETMAX (EMAX + NMAX)

// ---------------- scratch (device globals: allocation-free) ----------------
__device__ float g_h1[NMAX * 128];     // layer1 pre-act features [N,4,32]
__device__ float g_as1[NMAX * 4];      // alpha_src per (node, head)
__device__ float g_ad1[NMAX * 4];      // alpha_dst per (node, head)
__device__ float g_h2[NMAX * 2];       // layer2 features
__device__ float g_as2[NMAX];
__device__ float g_ad2[NMAX];
__device__ int   g_cnt[NMAX];          // in-degree (incl. self loop)
__device__ int   g_row[NMAX + 1];      // CSR row starts (by dst)
__device__ int   g_ofs[NMAX];          // scatter cursors
__device__ int   g_srcs[ETMAX];        // CSR column (src) indices

__device__ __forceinline__ float lrelu(float v) { return v > 0.f ? v : 0.2f * v; }

// ---------------- CSR build ------------------------------------------------
__global__ void k_init(int n) {
    int i = blockIdx.x * blockDim.x + threadIdx.x;
    if (i < n) g_cnt[i] = 1;            // the self loop
}
__global__ void k_hist(const int* __restrict__ ei, int Eo) {
    int e = blockIdx.x * blockDim.x + threadIdx.x;
    if (e < Eo) atomicAdd(g_cnt + ei[Eo + e], 1);
}
__global__ void k_scan(int n) {        // single block, 1024 threads
    __shared__ int sh[1024];
    int t = threadIdx.x;
    int chunk = (n + 1023) >> 10;
    int begin = t * chunk;
    int end = begin + chunk; if (end > n) end = n;
    int sum = 0;
    for (int i = begin; i < end && begin < n; i++) sum += g_cnt[i];
    sh[t] = sum;
    __syncthreads();
    #pragma unroll
    for (int off = 1; off < 1024; off <<= 1) {
        int v = (t >= off) ? sh[t - off] : 0;
        __syncthreads();
        sh[t] += v;
        __syncthreads();
    }
    int run = sh[t] - sum;             // exclusive prefix of this chunk
    if (begin < n) {
        for (int i = begin; i < end; i++) {
            int c = g_cnt[i];
            g_row[i] = run; g_ofs[i] = run;
            run += c;
        }
        if (end == n) g_row[n] = run;
    }
}
__global__ void k_scatter(const int* __restrict__ ei, int Eo, int n) {
    int e = blockIdx.x * blockDim.x + threadIdx.x;
    int ET = Eo + n;
    if (e >= ET) return;
    int s, d;
    if (e < Eo) { s = ei[e]; d = ei[Eo + e]; }
    else        { s = e - Eo; d = s; }
    int pos = atomicAdd(g_ofs + d, 1);
    g_srcs[pos] = s;
}

// ---------------- layer1 feature transform + attention logits ---------------
__global__ void k_feat1(const float* __restrict__ x, const float* __restrict__ W1,
                        const float* __restrict__ a_src1, const float* __restrict__ a_dst1,
                        int n_nodes) {
    __shared__ float Ws[16 * 128];
    int c = threadIdx.x;
    for (int i = c; i < 16 * 128; i += 128) Ws[i] = W1[i];
    __syncthreads();
    int lane = c & 31, head = c >> 5;
    float as = a_src1[c], ad = a_dst1[c];
    for (int n = blockIdx.x; n < n_nodes; n += gridDim.x) {
        const float4* xr = (const float4*)(x + (size_t)n * 16);
        float4 x0 = xr[0], x1 = xr[1], x2 = xr[2], x3 = xr[3];
        float acc;
        acc  = x0.x * Ws[c];        acc += x0.y * Ws[128 + c];
        acc += x0.z * Ws[256 + c];  acc += x0.w * Ws[384 + c];
        acc += x1.x * Ws[512 + c];  acc += x1.y * Ws[640 + c];
        acc += x1.z * Ws[768 + c];  acc += x1.w * Ws[896 + c];
        acc += x2.x * Ws[1024 + c]; acc += x2.y * Ws[1152 + c];
        acc += x2.z * Ws[1280 + c]; acc += x2.w * Ws[1408 + c];
        acc += x3.x * Ws[1536 + c]; acc += x3.y * Ws[1664 + c];
        acc += x3.z * Ws[1792 + c]; acc += x3.w * Ws[1920 + c];
        g_h1[(size_t)n * 128 + c] = acc;
        float s = acc * as, d = acc * ad;
        #pragma unroll
        for (int o = 16; o; o >>= 1) {
            s += __shfl_down_sync(0xffffffffu, s, o);
            d += __shfl_down_sync(0xffffffffu, d, o);
        }
        if (lane == 0) { g_as1[n * 4 + head] = s; g_ad1[n * 4 + head] = d; }
    }
}

// ---------------- fused layer1 gather + normalize + relu + layer2 proj ------
// one warp per dst node; lane owns channels [lane*4, lane*4+4).
__global__ void k_gather1(const float* __restrict__ b1, const float* __restrict__ W2,
                          const float* __restrict__ a_src2, const float* __restrict__ a_dst2,
                          int n_nodes) {
    int t = blockIdx.x * blockDim.x + threadIdx.x;
    int d = t >> 5, lane = t & 31;
    if (d >= n_nodes) return;
    int head = lane >> 3;
    int c0 = lane * 4;

    float adh = g_ad1[d * 4 + head];
    float ax = 0.f, ay = 0.f, az = 0.f, aw = 0.f, den = 0.f;

    int p = g_row[d], pend = g_row[d + 1];
    for (; p < pend; ++p) {
        int s = __ldg(g_srcs + p);                       // broadcast within warp
        float w = __expf(lrelu(__ldg(g_as1 + s * 4 + head) + adh));
        den += w;
        float4 h = *(const float4*)(g_h1 + (size_t)s * 128 + c0);
        ax = fmaf(w, h.x, ax); ay = fmaf(w, h.y, ay);
        az = fmaf(w, h.z, az); aw = fmaf(w, h.w, aw);
    }
    float inv = 1.f / (den + 1e-16f);
    // bias + relu
    float4 bb = *(const float4*)(b1 + c0);
    float v0 = fmaxf(ax * inv + bb.x, 0.f);
    float v1 = fmaxf(ay * inv + bb.y, 0.f);
    float v2 = fmaxf(az * inv + bb.z, 0.f);
    float v3 = fmaxf(aw * inv + bb.w, 0.f);
    // W2 projection: each lane's 4 channels x 2 outputs
    float4 wA = *(const float4*)(W2 + c0 * 2);           // [c0..c0+1] x 2
    float4 wB = *(const float4*)(W2 + c0 * 2 + 4);       // [c0+2..c0+3] x 2
    float pq0 = v0 * wA.x + v1 * wA.z + v2 * wB.x + v3 * wB.z;
    float pq1 = v0 * wA.y + v1 * wA.w + v2 * wB.y + v3 * wB.w;
    #pragma unroll
    for (int o = 16; o; o >>= 1) {
        pq0 += __shfl_down_sync(0xffffffffu, pq0, o);
        pq1 += __shfl_down_sync(0xffffffffu, pq1, o);
    }
    if (lane == 0) {
        g_h2[d * 2] = pq0; g_h2[d * 2 + 1] = pq1;
        g_as2[d] = pq0 * a_src2[0] + pq1 * a_src2[1];
        g_ad2[d] = pq0 * a_dst2[0] + pq1 * a_dst2[1];
    }
}

// ---------------- layer2 gather -> final output -----------------------------
// one warp per dst node; lanes stride over incoming edges.
__global__ void k_gather2(float* __restrict__ out, const float* __restrict__ b2,
                          int n_nodes) {
    int t = blockIdx.x * blockDim.x + threadIdx.x;
    int d = t >> 5, lane = t & 31;
    if (d >= n_nodes) return;
    float add = g_ad2[d];
    float wsum = 0.f, s0 = 0.f, s1 = 0.f;
    int p0 = g_row[d], pend = g_row[d + 1];
    for (int p = p0 + lane; p < pend; p += 32) {
        int s = __ldg(g_srcs + p);
        float w = __expf(lrelu(__ldg(g_as2 + s) + add));
        wsum += w;
        s0 = fmaf(w, __ldg(g_h2 + s * 2), s0);
        s1 = fmaf(w, __ldg(g_h2 + s * 2 + 1), s1);
    }
    #pragma unroll
    for (int o = 16; o; o >>= 1) {
        wsum += __shfl_down_sync(0xffffffffu, wsum, o);
        s0   += __shfl_down_sync(0xffffffffu, s0, o);
        s1   += __shfl_down_sync(0xffffffffu, s1, o);
    }
    if (lane == 0) {
        float inv = 1.f / (wsum + 1e-16f);
        out[d * 2]     = s0 * inv + b2[0];
        out[d * 2 + 1] = s1 * inv + b2[1];
    }
}

extern "C" void kernel_launch(void* const* d_in, const int* in_sizes, int n_in,
                              void* d_out, int out_size) {
    const float* x   = (const float*)d_in[0];
    const int*   ei  = (const int*)d_in[1];
    const float* W1  = (const float*)d_in[2];
    const float* as1 = (const float*)d_in[3];
    const float* ad1 = (const float*)d_in[4];
    const float* b1  = (const float*)d_in[5];
    const float* W2  = (const float*)d_in[6];
    const float* as2 = (const float*)d_in[7];
    const float* ad2 = (const float*)d_in[8];
    const float* b2  = (const float*)d_in[9];
    float* out = (float*)d_out;

    int n  = in_sizes[0] / 16;   // nodes
    int Eo = in_sizes[1] / 2;    // original edges
    int ET = Eo + n;

    // CSR build (by dst)
    k_init<<<(n + 255) / 256, 256>>>(n);
    k_hist<<<(Eo + 255) / 256, 256>>>(ei, Eo);
    k_scan<<<1, 1024>>>(n);
    k_scatter<<<(ET + 255) / 256, 256>>>(ei, Eo, n);

    // features (independent of CSR, same stream ordering is fine)
    k_feat1<<<1184, 128>>>(x, W1, as1, ad1, n);

    // fused gathers
    int warps_grid = (n * 32 + 255) / 256;
    k_gather1<<<warps_grid, 256>>>(b1, W2, as2, ad2, n);
    k_gather2<<<warps_grid, 256>>>(out, b2, n);
}

// round 4
// speedup vs baseline: 1.8494x; 1.7775x over previous
#include <cuda_runtime.h>
#include <cstdint>

#define NMAX 50000
#define EMAX 800000
#define ETMAX (EMAX + NMAX)
#define NBLK_MAX ((NMAX + 255) / 256)

// ---------------- scratch (device globals: allocation-free) ----------------
__device__ float g_h1[NMAX * 128];     // layer1 pre-act features [N,4,32]
__device__ float g_as1[NMAX * 4];      // alpha_src per (node, head)
__device__ float g_ad1[NMAX * 4];      // alpha_dst per (node, head)
__device__ float g_h2[NMAX * 2];       // layer2 features
__device__ float g_as2[NMAX];
__device__ float g_ad2[NMAX];
__device__ int   g_cnt[NMAX];          // in-degree (incl. self loop)
__device__ int   g_row[NMAX + 1];      // CSR row starts (by dst)
__device__ int   g_ofs[NMAX];          // scatter cursors
__device__ int   g_srcs[ETMAX];        // CSR column (src) indices
__device__ int   g_blk[NBLK_MAX];      // per-block count sums
__device__ int   g_blkpre[NBLK_MAX];   // exclusive prefix of block sums

__device__ __forceinline__ float lrelu(float v) { return v > 0.f ? v : 0.2f * v; }

// ---------------- CSR build ------------------------------------------------
__global__ void k_init(int n) {
    int i = blockIdx.x * blockDim.x + threadIdx.x;
    if (i < n) g_cnt[i] = 1;            // the self loop
}
__global__ void k_hist(const int* __restrict__ ei, int Eo) {
    int e = blockIdx.x * blockDim.x + threadIdx.x;
    if (e < Eo) atomicAdd(g_cnt + ei[Eo + e], 1);
}
// pass 1: per-block sums of g_cnt
__global__ void k_scan1(int n) {
    __shared__ int sh[256];
    int i = blockIdx.x * 256 + threadIdx.x;
    sh[threadIdx.x] = (i < n) ? g_cnt[i] : 0;
    __syncthreads();
    #pragma unroll
    for (int off = 128; off; off >>= 1) {
        if (threadIdx.x < off) sh[threadIdx.x] += sh[threadIdx.x + off];
        __syncthreads();
    }
    if (threadIdx.x == 0) g_blk[blockIdx.x] = sh[0];
}
// pass 2: single-block scan of the spine (nblk <= 512)
__global__ void k_scan2(int nblk) {
    __shared__ int sh[512];
    int t = threadIdx.x;
    int v = (t < nblk) ? g_blk[t] : 0;
    sh[t] = v;
    __syncthreads();
    #pragma unroll
    for (int off = 1; off < 512; off <<= 1) {
        int u = (t >= off) ? sh[t - off] : 0;
        __syncthreads();
        sh[t] += u;
        __syncthreads();
    }
    if (t < nblk) g_blkpre[t] = sh[t] - v;   // exclusive
}
// pass 3: per-block exclusive scan + spine offset -> row starts / cursors
__global__ void k_scan3(int n) {
    __shared__ int sh[256];
    int i = blockIdx.x * 256 + threadIdx.x;
    int v = (i < n) ? g_cnt[i] : 0;
    sh[threadIdx.x] = v;
    __syncthreads();
    #pragma unroll
    for (int off = 1; off < 256; off <<= 1) {
        int u = (threadIdx.x >= off) ? sh[threadIdx.x - off] : 0;
        __syncthreads();
        sh[threadIdx.x] += u;
        __syncthreads();
    }
    if (i < n) {
        int pre = g_blkpre[blockIdx.x] + sh[threadIdx.x] - v;
        g_row[i] = pre;
        g_ofs[i] = pre;
        if (i == n - 1) g_row[n] = pre + v;
    }
}
__global__ void k_scatter(const int* __restrict__ ei, int Eo, int n) {
    int e = blockIdx.x * blockDim.x + threadIdx.x;
    int ET = Eo + n;
    if (e >= ET) return;
    int s, d;
    if (e < Eo) { s = ei[e]; d = ei[Eo + e]; }
    else        { s = e - Eo; d = s; }
    int pos = atomicAdd(g_ofs + d, 1);
    g_srcs[pos] = s;
}

// ---------------- layer1 feature transform + attention logits ---------------
__global__ void k_feat1(const float* __restrict__ x, const float* __restrict__ W1,
                        const float* __restrict__ a_src1, const float* __restrict__ a_dst1,
                        int n_nodes) {
    __shared__ float Ws[16 * 128];
    int c = threadIdx.x;
    for (int i = c; i < 16 * 128; i += 128) Ws[i] = W1[i];
    __syncthreads();
    int lane = c & 31, head = c >> 5;
    float as = a_src1[c], ad = a_dst1[c];
    for (int n = blockIdx.x; n < n_nodes; n += gridDim.x) {
        const float4* xr = (const float4*)(x + (size_t)n * 16);
        float4 x0 = xr[0], x1 = xr[1], x2 = xr[2], x3 = xr[3];
        float acc;
        acc  = x0.x * Ws[c];        acc += x0.y * Ws[128 + c];
        acc += x0.z * Ws[256 + c];  acc += x0.w * Ws[384 + c];
        acc += x1.x * Ws[512 + c];  acc += x1.y * Ws[640 + c];
        acc += x1.z * Ws[768 + c];  acc += x1.w * Ws[896 + c];
        acc += x2.x * Ws[1024 + c]; acc += x2.y * Ws[1152 + c];
        acc += x2.z * Ws[1280 + c]; acc += x2.w * Ws[1408 + c];
        acc += x3.x * Ws[1536 + c]; acc += x3.y * Ws[1664 + c];
        acc += x3.z * Ws[1792 + c]; acc += x3.w * Ws[1920 + c];
        g_h1[(size_t)n * 128 + c] = acc;
        float s = acc * as, d = acc * ad;
        #pragma unroll
        for (int o = 16; o; o >>= 1) {
            s += __shfl_down_sync(0xffffffffu, s, o);
            d += __shfl_down_sync(0xffffffffu, d, o);
        }
        if (lane == 0) { g_as1[n * 4 + head] = s; g_ad1[n * 4 + head] = d; }
    }
}

// ---------------- fused layer1 gather + normalize + relu + layer2 proj ------
// one warp per dst node; lane owns channels [lane*4, lane*4+4).
// Edge loop unrolled x4 so 4 independent 512B gathers are in flight (MLP).
__global__ void k_gather1(const float* __restrict__ b1, const float* __restrict__ W2,
                          const float* __restrict__ a_src2, const float* __restrict__ a_dst2,
                          int n_nodes) {
    int t = blockIdx.x * blockDim.x + threadIdx.x;
    int d = t >> 5, lane = t & 31;
    if (d >= n_nodes) return;
    int head = lane >> 3;
    int c0 = lane * 4;

    float adh = g_ad1[d * 4 + head];
    float ax = 0.f, ay = 0.f, az = 0.f, aw = 0.f, den = 0.f;

    int p = g_row[d], pend = g_row[d + 1];
    for (; p + 4 <= pend; p += 4) {
        int s0 = __ldg(g_srcs + p);
        int s1 = __ldg(g_srcs + p + 1);
        int s2 = __ldg(g_srcs + p + 2);
        int s3 = __ldg(g_srcs + p + 3);
        float l0 = __ldg(g_as1 + s0 * 4 + head);
        float l1 = __ldg(g_as1 + s1 * 4 + head);
        float l2 = __ldg(g_as1 + s2 * 4 + head);
        float l3 = __ldg(g_as1 + s3 * 4 + head);
        float4 h0 = *(const float4*)(g_h1 + (size_t)s0 * 128 + c0);
        float4 h1 = *(const float4*)(g_h1 + (size_t)s1 * 128 + c0);
        float4 h2 = *(const float4*)(g_h1 + (size_t)s2 * 128 + c0);
        float4 h3 = *(const float4*)(g_h1 + (size_t)s3 * 128 + c0);
        float w0 = __expf(lrelu(l0 + adh));
        float w1 = __expf(lrelu(l1 + adh));
        float w2 = __expf(lrelu(l2 + adh));
        float w3 = __expf(lrelu(l3 + adh));
        den += (w0 + w1) + (w2 + w3);
        ax = fmaf(w0, h0.x, ax); ay = fmaf(w0, h0.y, ay);
        az = fmaf(w0, h0.z, az); aw = fmaf(w0, h0.w, aw);
        ax = fmaf(w1, h1.x, ax); ay = fmaf(w1, h1.y, ay);
        az = fmaf(w1, h1.z, az); aw = fmaf(w1, h1.w, aw);
        ax = fmaf(w2, h2.x, ax); ay = fmaf(w2, h2.y, ay);
        az = fmaf(w2, h2.z, az); aw = fmaf(w2, h2.w, aw);
        ax = fmaf(w3, h3.x, ax); ay = fmaf(w3, h3.y, ay);
        az = fmaf(w3, h3.z, az); aw = fmaf(w3, h3.w, aw);
    }
    for (; p < pend; ++p) {
        int s = __ldg(g_srcs + p);
        float w = __expf(lrelu(__ldg(g_as1 + s * 4 + head) + adh));
        den += w;
        float4 h = *(const float4*)(g_h1 + (size_t)s * 128 + c0);
        ax = fmaf(w, h.x, ax); ay = fmaf(w, h.y, ay);
        az = fmaf(w, h.z, az); aw = fmaf(w, h.w, aw);
    }
    float inv = 1.f / (den + 1e-16f);
    float4 bb = *(const float4*)(b1 + c0);
    float v0 = fmaxf(ax * inv + bb.x, 0.f);
    float v1 = fmaxf(ay * inv + bb.y, 0.f);
    float v2 = fmaxf(az * inv + bb.z, 0.f);
    float v3 = fmaxf(aw * inv + bb.w, 0.f);
    float4 wA = *(const float4*)(W2 + c0 * 2);
    float4 wB = *(const float4*)(W2 + c0 * 2 + 4);
    float pq0 = v0 * wA.x + v1 * wA.z + v2 * wB.x + v3 * wB.z;
    float pq1 = v0 * wA.y + v1 * wA.w + v2 * wB.y + v3 * wB.w;
    #pragma unroll
    for (int o = 16; o; o >>= 1) {
        pq0 += __shfl_down_sync(0xffffffffu, pq0, o);
        pq1 += __shfl_down_sync(0xffffffffu, pq1, o);
    }
    if (lane == 0) {
        g_h2[d * 2] = pq0; g_h2[d * 2 + 1] = pq1;
        g_as2[d] = pq0 * a_src2[0] + pq1 * a_src2[1];
        g_ad2[d] = pq0 * a_dst2[0] + pq1 * a_dst2[1];
    }
}

// ---------------- layer2 gather -> final output -----------------------------
__global__ void k_gather2(float* __restrict__ out, const float* __restrict__ b2,
                          int n_nodes) {
    int t = blockIdx.x * blockDim.x + threadIdx.x;
    int d = t >> 5, lane = t & 31;
    if (d >= n_nodes) return;
    float add = g_ad2[d];
    float wsum = 0.f, s0 = 0.f, s1 = 0.f;
    int p0 = g_row[d], pend = g_row[d + 1];
    for (int p = p0 + lane; p < pend; p += 32) {
        int s = __ldg(g_srcs + p);
        float w = __expf(lrelu(__ldg(g_as2 + s) + add));
        wsum += w;
        float2 h = *(const float2*)(g_h2 + s * 2);
        s0 = fmaf(w, h.x, s0);
        s1 = fmaf(w, h.y, s1);
    }
    #pragma unroll
    for (int o = 16; o; o >>= 1) {
        wsum += __shfl_down_sync(0xffffffffu, wsum, o);
        s0   += __shfl_down_sync(0xffffffffu, s0, o);
        s1   += __shfl_down_sync(0xffffffffu, s1, o);
    }
    if (lane == 0) {
        float inv = 1.f / (wsum + 1e-16f);
        out[d * 2]     = s0 * inv + b2[0];
        out[d * 2 + 1] = s1 * inv + b2[1];
    }
}

extern "C" void kernel_launch(void* const* d_in, const int* in_sizes, int n_in,
                              void* d_out, int out_size) {
    const float* x   = (const float*)d_in[0];
    const int*   ei  = (const int*)d_in[1];
    const float* W1  = (const float*)d_in[2];
    const float* as1 = (const float*)d_in[3];
    const float* ad1 = (const float*)d_in[4];
    const float* b1  = (const float*)d_in[5];
    const float* W2  = (const float*)d_in[6];
    const float* as2 = (const float*)d_in[7];
    const float* ad2 = (const float*)d_in[8];
    const float* b2  = (const float*)d_in[9];
    float* out = (float*)d_out;

    int n  = in_sizes[0] / 16;   // nodes
    int Eo = in_sizes[1] / 2;    // original edges
    int ET = Eo + n;
    int nblk = (n + 255) / 256;

    // CSR build (by dst)
    k_init<<<(n + 255) / 256, 256>>>(n);
    k_hist<<<(Eo + 255) / 256, 256>>>(ei, Eo);
    k_scan1<<<nblk, 256>>>(n);
    k_scan2<<<1, 512>>>(nblk);
    k_scan3<<<nblk, 256>>>(n);
    k_scatter<<<(ET + 255) / 256, 256>>>(ei, Eo, n);

    // features
    k_feat1<<<1184, 128>>>(x, W1, as1, ad1, n);

    // fused gathers
    int warps_grid = (n * 32 + 255) / 256;
    k_gather1<<<warps_grid, 256>>>(b1, W2, as2, ad2, n);
    k_gather2<<<warps_grid, 256>>>(out, b2, n);
}